// round 1
// baseline (speedup 1.0000x reference)
#include <cuda_runtime.h>
#include <cuda_bf16.h>
#include <math.h>

// ============================================================================
// Problem constants (shapes fixed by the dataset)
// ============================================================================
#define NMAX   20000
#define EMAX   320000
#define DMAX   512
#define HMAX   8

// ============================================================================
// Scratch (static device globals — no runtime allocation allowed)
// ============================================================================
__device__ int   g_src[EMAX];
__device__ int   g_dst[EMAX];
__device__ float g_h   [(size_t)NMAX * DMAX];   // transformed features (GEMM out)
__device__ float g_aggr[(size_t)NMAX * DMAX];   // aggregation output
__device__ float g_feat[(size_t)NMAX * DMAX];   // elu(out + b) -> next layer input
__device__ float g_als [NMAX * HMAX];
__device__ float g_ald [NMAX * HMAX];
__device__ float g_m   [NMAX * HMAX];
__device__ float g_z   [NMAX * HMAX];
__device__ float g_es  [NMAX * HMAX];           // self-edge logit
__device__ float g_ex  [(size_t)EMAX * HMAX];   // exp(e - m[dst]) per edge

// ============================================================================
// Helpers
// ============================================================================
__device__ __forceinline__ float lrelu(float x) { return x > 0.f ? x : 0.2f * x; }

__device__ __forceinline__ void atomicMaxFloat(float* addr, float v) {
    int* ia = (int*)addr;
    int old = *ia;
    while (__int_as_float(old) < v) {
        int assumed = old;
        old = atomicCAS(ia, assumed, __float_as_int(v));
        if (old == assumed) break;
    }
}

// ============================================================================
// Edge index conversion: detect int64 vs int32 at runtime, emit int32 src/dst.
// int64 little-endian: odd 32-bit words of the first 64 are all zero (values <
// 2^31). Random int32 node ids make that pattern astronomically unlikely.
// ============================================================================
__global__ void k_convert(const unsigned int* __restrict__ w, int E) {
    bool is64 = true;
    #pragma unroll
    for (int i = 1; i < 64; i += 2) {
        if (w[i] != 0u) { is64 = false; break; }
    }
    int e = blockIdx.x * blockDim.x + threadIdx.x;
    if (e < E) {
        if (is64) {
            g_src[e] = (int)w[2 * e];
            g_dst[e] = (int)w[2 * (E + e)];
        } else {
            g_src[e] = (int)w[e];
            g_dst[e] = (int)w[E + e];
        }
    }
}

// ============================================================================
// SGEMM: C[M,N] = A[M,K] @ B[K,N], row-major, fp32.
// BM=128, BN=64, BK=16, 256 threads, 8x4 micro-tile per thread.
// ============================================================================
#define BM 128
#define BN 64
#define BK 16

__global__ __launch_bounds__(256) void k_sgemm(
    const float* __restrict__ A, const float* __restrict__ B,
    float* __restrict__ C, int M, int N, int K)
{
    __shared__ float As[BK][BM];
    __shared__ float Bs[BK][BN];

    const int tid  = threadIdx.x;
    const int row0 = blockIdx.y * BM;
    const int col0 = blockIdx.x * BN;
    const int tx = tid & 15;   // 0..15 -> column group (4 cols each)
    const int ty = tid >> 4;   // 0..15 -> row group (8 rows each)

    float acc[8][4];
    #pragma unroll
    for (int i = 0; i < 8; i++)
        #pragma unroll
        for (int j = 0; j < 4; j++) acc[i][j] = 0.f;

    for (int k0 = 0; k0 < K; k0 += BK) {
        // Load A tile: 128x16 = 2048 elems, 8 per thread
        #pragma unroll
        for (int p = 0; p < 8; p++) {
            int idx = tid + p * 256;
            int m = idx >> 4, kk = idx & 15;
            int gm = row0 + m, gk = k0 + kk;
            As[kk][m] = (gm < M && gk < K) ? A[(size_t)gm * K + gk] : 0.f;
        }
        // Load B tile: 16x64 = 1024 elems, 4 per thread
        #pragma unroll
        for (int p = 0; p < 4; p++) {
            int idx = tid + p * 256;
            int kk = idx >> 6, n = idx & 63;
            int gk = k0 + kk, gn = col0 + n;
            Bs[kk][n] = (gk < K && gn < N) ? B[(size_t)gk * N + gn] : 0.f;
        }
        __syncthreads();

        #pragma unroll
        for (int kk = 0; kk < BK; kk++) {
            float4 a0 = *(const float4*)&As[kk][ty * 8];
            float4 a1 = *(const float4*)&As[kk][ty * 8 + 4];
            float4 b0 = *(const float4*)&Bs[kk][tx * 4];
            float ar[8] = {a0.x, a0.y, a0.z, a0.w, a1.x, a1.y, a1.z, a1.w};
            float br[4] = {b0.x, b0.y, b0.z, b0.w};
            #pragma unroll
            for (int i = 0; i < 8; i++)
                #pragma unroll
                for (int j = 0; j < 4; j++)
                    acc[i][j] = fmaf(ar[i], br[j], acc[i][j]);
        }
        __syncthreads();
    }

    #pragma unroll
    for (int i = 0; i < 8; i++) {
        int gm = row0 + ty * 8 + i;
        if (gm >= M) continue;
        #pragma unroll
        for (int j = 0; j < 4; j++) {
            int gn = col0 + tx * 4 + j;
            if (gn < N) C[(size_t)gm * N + gn] = acc[i][j];
        }
    }
}

// ============================================================================
// Attention scalar dots: al_s[n,h] = sum_c h[n,h,c]*a_src[h,c] (same for dst)
// One block per node.
// ============================================================================
__global__ void k_dots(const float* __restrict__ h,
                       const float* __restrict__ asrc,
                       const float* __restrict__ adst,
                       int Nn, int H, int C)
{
    int n = blockIdx.x;
    if (n >= Nn) return;
    __shared__ float sh[64];
    const int D = H * C;
    for (int hh = 0; hh < H; hh++) {
        float ls = 0.f, ld = 0.f;
        for (int c = threadIdx.x; c < C; c += blockDim.x) {
            float v = h[(size_t)n * D + hh * C + c];
            ls = fmaf(v, asrc[hh * C + c], ls);
            ld = fmaf(v, adst[hh * C + c], ld);
        }
        #pragma unroll
        for (int o = 16; o > 0; o >>= 1) {
            ls += __shfl_down_sync(0xffffffffu, ls, o);
            ld += __shfl_down_sync(0xffffffffu, ld, o);
        }
        int lane = threadIdx.x & 31, wid = threadIdx.x >> 5;
        if (lane == 0) { sh[wid] = ls; sh[32 + wid] = ld; }
        __syncthreads();
        if (threadIdx.x == 0) {
            float a = 0.f, b = 0.f;
            int nw = blockDim.x >> 5;
            for (int i = 0; i < nw; i++) { a += sh[i]; b += sh[32 + i]; }
            g_als[n * H + hh] = a;
            g_ald[n * H + hh] = b;
        }
        __syncthreads();
    }
}

// ============================================================================
// Softmax bookkeeping
// ============================================================================
__global__ void k_self_init(int total) {   // total = N*H
    int i = blockIdx.x * blockDim.x + threadIdx.x;
    if (i >= total) return;
    float e = lrelu(g_als[i] + g_ald[i]);  // self edge (i,i)
    g_es[i] = e;
    g_m[i]  = e;
}

__global__ void k_edge_max(int E, int H) {
    int idx = blockIdx.x * blockDim.x + threadIdx.x;
    if (idx >= E * H) return;
    int e = idx / H, hh = idx - e * H;
    int s = g_src[e], t = g_dst[e];
    float v = lrelu(g_als[s * H + hh] + g_ald[t * H + hh]);
    atomicMaxFloat(&g_m[t * H + hh], v);
}

__global__ void k_z_init(int total) {
    int i = blockIdx.x * blockDim.x + threadIdx.x;
    if (i >= total) return;
    g_z[i] = expf(g_es[i] - g_m[i]);
}

__global__ void k_edge_exp(int E, int H) {
    int idx = blockIdx.x * blockDim.x + threadIdx.x;
    if (idx >= E * H) return;
    int e = idx / H, hh = idx - e * H;
    int s = g_src[e], t = g_dst[e];
    float v  = lrelu(g_als[s * H + hh] + g_ald[t * H + hh]);
    float ex = expf(v - g_m[t * H + hh]);
    g_ex[idx] = ex;
    atomicAdd(&g_z[t * H + hh], ex);
}

// ============================================================================
// Aggregation
// ============================================================================
template <int H, int C>
__global__ void k_self_agg(const float* __restrict__ h, float* __restrict__ out) {
    constexpr int D = H * C;
    int n = blockIdx.x;
    __shared__ float al[H];
    if (threadIdx.x < H) {
        int i = n * H + threadIdx.x;
        al[threadIdx.x] = expf(g_es[i] - g_m[i]) / (g_z[i] + 1e-16f);
    }
    __syncthreads();
    for (int d = threadIdx.x; d < D; d += blockDim.x)
        out[(size_t)n * D + d] = al[d / C] * h[(size_t)n * D + d];
}

template <int H, int C>
__global__ void k_edge_agg(const float* __restrict__ h, float* __restrict__ out) {
    constexpr int D = H * C;
    int e = blockIdx.x;
    int s = g_src[e], t = g_dst[e];
    __shared__ float al[H];
    if (threadIdx.x < H)
        al[threadIdx.x] = g_ex[(size_t)e * H + threadIdx.x] /
                          (g_z[t * H + threadIdx.x] + 1e-16f);
    __syncthreads();
    if (D % 4 == 0) {
        for (int d4 = threadIdx.x * 4; d4 < D; d4 += blockDim.x * 4) {
            float4 hv = *(const float4*)&h[(size_t)s * D + d4];
            float a = al[d4 / C];
            float* o = &out[(size_t)t * D + d4];
            atomicAdd(o + 0, a * hv.x);
            atomicAdd(o + 1, a * hv.y);
            atomicAdd(o + 2, a * hv.z);
            atomicAdd(o + 3, a * hv.w);
        }
    } else {
        for (int d = threadIdx.x; d < D; d += blockDim.x) {
            float a = al[d / C];
            atomicAdd(&out[(size_t)t * D + d], a * h[(size_t)s * D + d]);
        }
    }
}

// ============================================================================
// Elementwise epilogues
// ============================================================================
__global__ void k_bias_elu(const float* __restrict__ in, const float* __restrict__ b,
                           float* __restrict__ outp, int total, int D) {
    int i = blockIdx.x * blockDim.x + threadIdx.x;
    if (i >= total) return;
    float v = in[i] + b[i % D];
    outp[i] = v > 0.f ? v : expf(v) - 1.f;
}

__global__ void k_bias_add(float* __restrict__ outp, const float* __restrict__ b,
                           int total, int D) {
    int i = blockIdx.x * blockDim.x + threadIdx.x;
    if (i >= total) return;
    outp[i] += b[i % D];
}

// ============================================================================
// Host launch
// ============================================================================
static inline int cdiv(int a, int b) { return (a + b - 1) / b; }

extern "C" void kernel_launch(void* const* d_in, const int* in_sizes, int n_in,
                              void* d_out, int out_size) {
    const float* x   = (const float*)d_in[0];
    const void*  ei  = d_in[1];
    const float* W1  = (const float*)d_in[2];
    const float* a1s = (const float*)d_in[3];
    const float* a1d = (const float*)d_in[4];
    const float* b1  = (const float*)d_in[5];
    const float* W2  = (const float*)d_in[6];
    const float* a2s = (const float*)d_in[7];
    const float* a2d = (const float*)d_in[8];
    const float* b2  = (const float*)d_in[9];
    const float* W3  = (const float*)d_in[10];
    const float* a3s = (const float*)d_in[11];
    const float* a3d = (const float*)d_in[12];
    const float* b3  = (const float*)d_in[13];
    float* out = (float*)d_out;

    const int Nn = in_sizes[0] / 50;   // 20000
    const int E  = in_sizes[1] / 2;    // 320000 (element count same for i32/i64)

    float *h, *aggr, *feat;
    cudaGetSymbolAddress((void**)&h,    g_h);
    cudaGetSymbolAddress((void**)&aggr, g_aggr);
    cudaGetSymbolAddress((void**)&feat, g_feat);

    k_convert<<<cdiv(E, 256), 256>>>((const unsigned int*)ei, E);

    // ---------------- Layer 1: 50 -> 8 heads x 64, concat ----------------
    {
        const int H = 8, C = 64, D = 512;
        dim3 grid(cdiv(D, BN), cdiv(Nn, BM));
        k_sgemm<<<grid, 256>>>(x, W1, h, Nn, D, 50);
        k_dots<<<Nn, 128>>>(h, a1s, a1d, Nn, H, C);
        int nh = Nn * H;
        k_self_init<<<cdiv(nh, 256), 256>>>(nh);
        k_edge_max <<<cdiv(E * H, 256), 256>>>(E, H);
        k_z_init   <<<cdiv(nh, 256), 256>>>(nh);
        k_edge_exp <<<cdiv(E * H, 256), 256>>>(E, H);
        k_self_agg<8, 64><<<Nn, 128>>>(h, aggr);
        k_edge_agg<8, 64><<<E, 128>>>(h, aggr);
        k_bias_elu<<<cdiv(Nn * D, 256), 256>>>(aggr, b1, feat, Nn * D, D);
    }

    // ---------------- Layer 2: 512 -> 512, 1 head ----------------
    {
        const int H = 1, C = 512, D = 512;
        dim3 grid(cdiv(D, BN), cdiv(Nn, BM));
        k_sgemm<<<grid, 256>>>(feat, W2, h, Nn, D, 512);
        k_dots<<<Nn, 128>>>(h, a2s, a2d, Nn, H, C);
        int nh = Nn;
        k_self_init<<<cdiv(nh, 256), 256>>>(nh);
        k_edge_max <<<cdiv(E, 256), 256>>>(E, H);
        k_z_init   <<<cdiv(nh, 256), 256>>>(nh);
        k_edge_exp <<<cdiv(E, 256), 256>>>(E, H);
        k_self_agg<1, 512><<<Nn, 128>>>(h, aggr);
        k_edge_agg<1, 512><<<E, 128>>>(h, aggr);
        k_bias_elu<<<cdiv(Nn * D, 256), 256>>>(aggr, b2, feat, Nn * D, D);
    }

    // ---------------- Layer 3: 512 -> 121, 1 head, mean (=identity) ------
    {
        const int H = 1, C = 121, D = 121;
        dim3 grid(cdiv(D, BN), cdiv(Nn, BM));
        k_sgemm<<<grid, 256>>>(feat, W3, h, Nn, D, 512);
        k_dots<<<Nn, 128>>>(h, a3s, a3d, Nn, H, C);
        int nh = Nn;
        k_self_init<<<cdiv(nh, 256), 256>>>(nh);
        k_edge_max <<<cdiv(E, 256), 256>>>(E, H);
        k_z_init   <<<cdiv(nh, 256), 256>>>(nh);
        k_edge_exp <<<cdiv(E, 256), 256>>>(E, H);
        k_self_agg<1, 121><<<Nn, 128>>>(h, out);   // overwrites poison
        k_edge_agg<1, 121><<<E, 128>>>(h, out);
        k_bias_add<<<cdiv(Nn * D, 256), 256>>>(out, b3, Nn * D, D);
    }
}

// round 2
// speedup vs baseline: 1.0942x; 1.0942x over previous
#include <cuda_runtime.h>
#include <cuda_bf16.h>
#include <math.h>

// ============================================================================
// Problem constants (shapes fixed by the dataset)
// ============================================================================
#define NMAX   20000
#define EMAX   320000
#define DMAX   512
#define HMAX   8

// ============================================================================
// Scratch (static device globals — no runtime allocation allowed)
// ============================================================================
__device__ int   g_src[EMAX];
__device__ int   g_dst[EMAX];
__device__ float g_h   [(size_t)NMAX * DMAX];   // transformed features (GEMM out)
__device__ float g_aggr[(size_t)NMAX * DMAX];   // aggregation output
__device__ float g_feat[(size_t)NMAX * DMAX];   // elu(out + b) -> next layer input
__device__ float g_als [NMAX * HMAX];
__device__ float g_ald [NMAX * HMAX];
__device__ float g_m   [NMAX * HMAX];
__device__ float g_z   [NMAX * HMAX];
__device__ float g_es  [NMAX * HMAX];           // self-edge logit
__device__ float g_ex  [(size_t)EMAX * HMAX];   // exp(e - m[dst]) per edge

// ============================================================================
// Helpers
// ============================================================================
__device__ __forceinline__ float lrelu(float x) { return x > 0.f ? x : 0.2f * x; }

__device__ __forceinline__ void atomicMaxFloat(float* addr, float v) {
    int* ia = (int*)addr;
    int old = *ia;
    while (__int_as_float(old) < v) {
        int assumed = old;
        old = atomicCAS(ia, assumed, __float_as_int(v));
        if (old == assumed) break;
    }
}

__device__ __forceinline__ float tf32_rna(float x) {
    unsigned int r;
    asm("cvt.rna.tf32.f32 %0, %1;" : "=r"(r) : "f"(x));
    return __uint_as_float(r);
}

// ============================================================================
// Edge index conversion: detect int64 vs int32 at runtime, emit int32 src/dst.
// ============================================================================
__global__ void k_convert(const unsigned int* __restrict__ w, int E) {
    bool is64 = true;
    #pragma unroll
    for (int i = 1; i < 64; i += 2) {
        if (w[i] != 0u) { is64 = false; break; }
    }
    int e = blockIdx.x * blockDim.x + threadIdx.x;
    if (e < E) {
        if (is64) {
            g_src[e] = (int)w[2 * e];
            g_dst[e] = (int)w[2 * (E + e)];
        } else {
            g_src[e] = (int)w[e];
            g_dst[e] = (int)w[E + e];
        }
    }
}

// ============================================================================
// 3xTF32 tensor-core GEMM: C[M,N] = A[M,K] @ B[K,N], row-major fp32 in/out.
// Block tile 128x64, BK=16, 8 warps (warp tile 32x32 = 2x4 m16n8k8 tiles).
// hi/lo tf32 split (hi*hi + hi*lo + lo*hi) => ~fp32 accuracy.
// Double-buffered dynamic smem (51200 B), register-staged global loads.
// ============================================================================
#define GBM 128
#define GBN 64
#define GBK 16
#define BMp 132   // GBM + 4 pad
#define BNp 68    // GBN + 4 pad
#define ASZ (GBK * BMp)
#define BSZ (GBK * BNp)
#define GSMEM_BYTES ((4 * ASZ + 4 * BSZ) * 4)

__device__ __forceinline__ void mma_tf32(float c[4], const unsigned int a[4],
                                         const unsigned int b[2]) {
    asm volatile(
        "mma.sync.aligned.m16n8k8.row.col.f32.tf32.tf32.f32 "
        "{%0,%1,%2,%3}, {%4,%5,%6,%7}, {%8,%9}, {%0,%1,%2,%3};\n"
        : "+f"(c[0]), "+f"(c[1]), "+f"(c[2]), "+f"(c[3])
        : "r"(a[0]), "r"(a[1]), "r"(a[2]), "r"(a[3]), "r"(b[0]), "r"(b[1]));
}

__global__ __launch_bounds__(256, 2) void k_gemm_tf32(
    const float* __restrict__ A, const float* __restrict__ B,
    float* __restrict__ C, int M, int N, int K)
{
    extern __shared__ float s[];
    float* Ah = s;                  // [2][GBK][BMp]
    float* Al = s + 2 * ASZ;
    float* Bh = s + 4 * ASZ;        // [2][GBK][BNp]
    float* Bl = s + 4 * ASZ + 2 * BSZ;

    const int tid  = threadIdx.x;
    const int lane = tid & 31, warp = tid >> 5;
    const int wm = warp >> 1, wn = warp & 1;     // 4 x 2 warp grid
    const int g = lane >> 2, tq = lane & 3;
    const int row0 = blockIdx.y * GBM;
    const int col0 = blockIdx.x * GBN;

    // A staging map: thread -> (row, 8 consecutive k)
    const int arow = tid >> 1;
    const int akb  = (tid & 1) * 8;

    float c[2][4][4];
    #pragma unroll
    for (int i = 0; i < 2; i++)
        #pragma unroll
        for (int j = 0; j < 4; j++)
            #pragma unroll
            for (int q = 0; q < 4; q++) c[i][j][q] = 0.f;

    const int nIt = (K + GBK - 1) / GBK;
    float ra[8], rb[4];

    // ---- load tile 0 into regs ----
    {
        #pragma unroll
        for (int j = 0; j < 8; j++) {
            int gk = akb + j;
            ra[j] = (row0 + arow < M && gk < K)
                    ? A[(size_t)(row0 + arow) * K + gk] : 0.f;
        }
        #pragma unroll
        for (int p = 0; p < 4; p++) {
            int e = tid + p * 256, bk = e >> 6, bn = e & 63;
            rb[p] = (bk < K && col0 + bn < N)
                    ? B[(size_t)bk * N + col0 + bn] : 0.f;
        }
    }
    // ---- sts tile 0 -> buf 0 ----
    {
        #pragma unroll
        for (int j = 0; j < 8; j++) {
            float v = ra[j], h = tf32_rna(v), l = tf32_rna(v - h);
            int off = (akb + j) * BMp + arow;
            Ah[off] = h; Al[off] = l;
        }
        #pragma unroll
        for (int p = 0; p < 4; p++) {
            int e = tid + p * 256, bk = e >> 6, bn = e & 63;
            float v = rb[p], h = tf32_rna(v), l = tf32_rna(v - h);
            int off = bk * BNp + bn;
            Bh[off] = h; Bl[off] = l;
        }
    }
    __syncthreads();

    for (int it = 0; it < nIt; it++) {
        // stage next tile
        if (it + 1 < nIt) {
            int k0 = (it + 1) * GBK;
            #pragma unroll
            for (int j = 0; j < 8; j++) {
                int gk = k0 + akb + j;
                ra[j] = (row0 + arow < M && gk < K)
                        ? A[(size_t)(row0 + arow) * K + gk] : 0.f;
            }
            #pragma unroll
            for (int p = 0; p < 4; p++) {
                int e = tid + p * 256, bk = e >> 6, bn = e & 63;
                int gk = k0 + bk;
                rb[p] = (gk < K && col0 + bn < N)
                        ? B[(size_t)gk * N + col0 + bn] : 0.f;
            }
        }

        // compute on current buffer
        const int buf = it & 1;
        const float* ah_ = Ah + buf * ASZ;
        const float* al_ = Al + buf * ASZ;
        const float* bh_ = Bh + buf * BSZ;
        const float* bl_ = Bl + buf * BSZ;

        #pragma unroll
        for (int ks = 0; ks < 2; ks++) {
            const int kb = ks * 8;
            unsigned int afh[2][4], afl[2][4];
            #pragma unroll
            for (int tm = 0; tm < 2; tm++) {
                int m  = wm * 32 + tm * 16 + g;
                int o1 = (kb + tq) * BMp + m;
                int o2 = (kb + tq + 4) * BMp + m;
                afh[tm][0] = __float_as_uint(ah_[o1]);
                afh[tm][1] = __float_as_uint(ah_[o1 + 8]);
                afh[tm][2] = __float_as_uint(ah_[o2]);
                afh[tm][3] = __float_as_uint(ah_[o2 + 8]);
                afl[tm][0] = __float_as_uint(al_[o1]);
                afl[tm][1] = __float_as_uint(al_[o1 + 8]);
                afl[tm][2] = __float_as_uint(al_[o2]);
                afl[tm][3] = __float_as_uint(al_[o2 + 8]);
            }
            unsigned int bfh[4][2], bfl[4][2];
            #pragma unroll
            for (int tn = 0; tn < 4; tn++) {
                int n  = wn * 32 + tn * 8 + g;
                int o1 = (kb + tq) * BNp + n;
                int o2 = (kb + tq + 4) * BNp + n;
                bfh[tn][0] = __float_as_uint(bh_[o1]);
                bfh[tn][1] = __float_as_uint(bh_[o2]);
                bfl[tn][0] = __float_as_uint(bl_[o1]);
                bfl[tn][1] = __float_as_uint(bl_[o2]);
            }
            #pragma unroll
            for (int tm = 0; tm < 2; tm++)
                #pragma unroll
                for (int tn = 0; tn < 4; tn++) {
                    mma_tf32(c[tm][tn], afh[tm], bfh[tn]);
                    mma_tf32(c[tm][tn], afh[tm], bfl[tn]);
                    mma_tf32(c[tm][tn], afl[tm], bfh[tn]);
                }
        }

        // sts next tile into the other buffer
        if (it + 1 < nIt) {
            int nb = buf ^ 1;
            float* ahd = Ah + nb * ASZ;
            float* ald = Al + nb * ASZ;
            float* bhd = Bh + nb * BSZ;
            float* bld = Bl + nb * BSZ;
            #pragma unroll
            for (int j = 0; j < 8; j++) {
                float v = ra[j], h = tf32_rna(v), l = tf32_rna(v - h);
                int off = (akb + j) * BMp + arow;
                ahd[off] = h; ald[off] = l;
            }
            #pragma unroll
            for (int p = 0; p < 4; p++) {
                int e = tid + p * 256, bk = e >> 6, bn = e & 63;
                float v = rb[p], h = tf32_rna(v), l = tf32_rna(v - h);
                int off = bk * BNp + bn;
                bhd[off] = h; bld[off] = l;
            }
            __syncthreads();
        }
    }

    // ---- epilogue ----
    #pragma unroll
    for (int tm = 0; tm < 2; tm++) {
        #pragma unroll
        for (int tn = 0; tn < 4; tn++) {
            int gm0 = row0 + wm * 32 + tm * 16 + g;
            int gn0 = col0 + wn * 32 + tn * 8 + 2 * tq;
            if (gm0 < M) {
                if (gn0 < N)     C[(size_t)gm0 * N + gn0]     = c[tm][tn][0];
                if (gn0 + 1 < N) C[(size_t)gm0 * N + gn0 + 1] = c[tm][tn][1];
            }
            if (gm0 + 8 < M) {
                if (gn0 < N)     C[(size_t)(gm0 + 8) * N + gn0]     = c[tm][tn][2];
                if (gn0 + 1 < N) C[(size_t)(gm0 + 8) * N + gn0 + 1] = c[tm][tn][3];
            }
        }
    }
}

// ============================================================================
// Attention scalar dots: al_s[n,h] = sum_c h[n,h,c]*a_src[h,c] (same for dst)
// ============================================================================
__global__ void k_dots(const float* __restrict__ h,
                       const float* __restrict__ asrc,
                       const float* __restrict__ adst,
                       int Nn, int H, int C)
{
    int n = blockIdx.x;
    if (n >= Nn) return;
    __shared__ float sh[64];
    const int D = H * C;
    for (int hh = 0; hh < H; hh++) {
        float ls = 0.f, ld = 0.f;
        for (int c = threadIdx.x; c < C; c += blockDim.x) {
            float v = h[(size_t)n * D + hh * C + c];
            ls = fmaf(v, asrc[hh * C + c], ls);
            ld = fmaf(v, adst[hh * C + c], ld);
        }
        #pragma unroll
        for (int o = 16; o > 0; o >>= 1) {
            ls += __shfl_down_sync(0xffffffffu, ls, o);
            ld += __shfl_down_sync(0xffffffffu, ld, o);
        }
        int lane = threadIdx.x & 31, wid = threadIdx.x >> 5;
        if (lane == 0) { sh[wid] = ls; sh[32 + wid] = ld; }
        __syncthreads();
        if (threadIdx.x == 0) {
            float a = 0.f, b = 0.f;
            int nw = blockDim.x >> 5;
            for (int i = 0; i < nw; i++) { a += sh[i]; b += sh[32 + i]; }
            g_als[n * H + hh] = a;
            g_ald[n * H + hh] = b;
        }
        __syncthreads();
    }
}

// ============================================================================
// Softmax bookkeeping
// ============================================================================
__global__ void k_self_init(int total) {   // total = N*H
    int i = blockIdx.x * blockDim.x + threadIdx.x;
    if (i >= total) return;
    float e = lrelu(g_als[i] + g_ald[i]);  // self edge (i,i)
    g_es[i] = e;
    g_m[i]  = e;
}

__global__ void k_edge_max(int E, int H) {
    int idx = blockIdx.x * blockDim.x + threadIdx.x;
    if (idx >= E * H) return;
    int e = idx / H, hh = idx - e * H;
    int s = g_src[e], t = g_dst[e];
    float v = lrelu(g_als[s * H + hh] + g_ald[t * H + hh]);
    atomicMaxFloat(&g_m[t * H + hh], v);
}

__global__ void k_z_init(int total) {
    int i = blockIdx.x * blockDim.x + threadIdx.x;
    if (i >= total) return;
    g_z[i] = expf(g_es[i] - g_m[i]);
}

__global__ void k_edge_exp(int E, int H) {
    int idx = blockIdx.x * blockDim.x + threadIdx.x;
    if (idx >= E * H) return;
    int e = idx / H, hh = idx - e * H;
    int s = g_src[e], t = g_dst[e];
    float v  = lrelu(g_als[s * H + hh] + g_ald[t * H + hh]);
    float ex = expf(v - g_m[t * H + hh]);
    g_ex[idx] = ex;
    atomicAdd(&g_z[t * H + hh], ex);
}

// ============================================================================
// Aggregation
// ============================================================================
template <int H, int C>
__global__ void k_self_agg(const float* __restrict__ h, float* __restrict__ out) {
    constexpr int D = H * C;
    int n = blockIdx.x;
    __shared__ float al[H];
    if (threadIdx.x < H) {
        int i = n * H + threadIdx.x;
        al[threadIdx.x] = expf(g_es[i] - g_m[i]) / (g_z[i] + 1e-16f);
    }
    __syncthreads();
    for (int d = threadIdx.x; d < D; d += blockDim.x)
        out[(size_t)n * D + d] = al[d / C] * h[(size_t)n * D + d];
}

template <int H, int C>
__global__ void k_edge_agg(const float* __restrict__ h, float* __restrict__ out) {
    constexpr int D = H * C;
    int e = blockIdx.x;
    int s = g_src[e], t = g_dst[e];
    __shared__ float al[H];
    if (threadIdx.x < H)
        al[threadIdx.x] = g_ex[(size_t)e * H + threadIdx.x] /
                          (g_z[t * H + threadIdx.x] + 1e-16f);
    __syncthreads();
    if (D % 4 == 0) {
        for (int d4 = threadIdx.x * 4; d4 < D; d4 += blockDim.x * 4) {
            float4 hv = *(const float4*)&h[(size_t)s * D + d4];
            float a = al[d4 / C];
            float* o = &out[(size_t)t * D + d4];
            atomicAdd(o + 0, a * hv.x);
            atomicAdd(o + 1, a * hv.y);
            atomicAdd(o + 2, a * hv.z);
            atomicAdd(o + 3, a * hv.w);
        }
    } else {
        for (int d = threadIdx.x; d < D; d += blockDim.x) {
            float a = al[d / C];
            atomicAdd(&out[(size_t)t * D + d], a * h[(size_t)s * D + d]);
        }
    }
}

// ============================================================================
// Elementwise epilogues
// ============================================================================
__global__ void k_bias_elu(const float* __restrict__ in, const float* __restrict__ b,
                           float* __restrict__ outp, int total, int D) {
    int i = blockIdx.x * blockDim.x + threadIdx.x;
    if (i >= total) return;
    float v = in[i] + b[i % D];
    outp[i] = v > 0.f ? v : expf(v) - 1.f;
}

__global__ void k_bias_add(float* __restrict__ outp, const float* __restrict__ b,
                           int total, int D) {
    int i = blockIdx.x * blockDim.x + threadIdx.x;
    if (i >= total) return;
    outp[i] += b[i % D];
}

// ============================================================================
// Host launch
// ============================================================================
static inline int cdiv(int a, int b) { return (a + b - 1) / b; }

extern "C" void kernel_launch(void* const* d_in, const int* in_sizes, int n_in,
                              void* d_out, int out_size) {
    const float* x   = (const float*)d_in[0];
    const void*  ei  = d_in[1];
    const float* W1  = (const float*)d_in[2];
    const float* a1s = (const float*)d_in[3];
    const float* a1d = (const float*)d_in[4];
    const float* b1  = (const float*)d_in[5];
    const float* W2  = (const float*)d_in[6];
    const float* a2s = (const float*)d_in[7];
    const float* a2d = (const float*)d_in[8];
    const float* b2  = (const float*)d_in[9];
    const float* W3  = (const float*)d_in[10];
    const float* a3s = (const float*)d_in[11];
    const float* a3d = (const float*)d_in[12];
    const float* b3  = (const float*)d_in[13];
    float* out = (float*)d_out;

    const int Nn = in_sizes[0] / 50;   // 20000
    const int E  = in_sizes[1] / 2;    // 320000

    float *h, *aggr, *feat;
    cudaGetSymbolAddress((void**)&h,    g_h);
    cudaGetSymbolAddress((void**)&aggr, g_aggr);
    cudaGetSymbolAddress((void**)&feat, g_feat);

    cudaFuncSetAttribute(k_gemm_tf32,
                         cudaFuncAttributeMaxDynamicSharedMemorySize, GSMEM_BYTES);

    k_convert<<<cdiv(E, 256), 256>>>((const unsigned int*)ei, E);

    // ---------------- Layer 1: 50 -> 8 heads x 64, concat ----------------
    {
        const int H = 8, C = 64, D = 512;
        dim3 grid(cdiv(D, GBN), cdiv(Nn, GBM));
        k_gemm_tf32<<<grid, 256, GSMEM_BYTES>>>(x, W1, h, Nn, D, 50);
        k_dots<<<Nn, 128>>>(h, a1s, a1d, Nn, H, C);
        int nh = Nn * H;
        k_self_init<<<cdiv(nh, 256), 256>>>(nh);
        k_edge_max <<<cdiv(E * H, 256), 256>>>(E, H);
        k_z_init   <<<cdiv(nh, 256), 256>>>(nh);
        k_edge_exp <<<cdiv(E * H, 256), 256>>>(E, H);
        k_self_agg<8, 64><<<Nn, 128>>>(h, aggr);
        k_edge_agg<8, 64><<<E, 128>>>(h, aggr);
        k_bias_elu<<<cdiv(Nn * D, 256), 256>>>(aggr, b1, feat, Nn * D, D);
    }

    // ---------------- Layer 2: 512 -> 512, 1 head ----------------
    {
        const int H = 1, C = 512, D = 512;
        dim3 grid(cdiv(D, GBN), cdiv(Nn, GBM));
        k_gemm_tf32<<<grid, 256, GSMEM_BYTES>>>(feat, W2, h, Nn, D, 512);
        k_dots<<<Nn, 128>>>(h, a2s, a2d, Nn, H, C);
        int nh = Nn;
        k_self_init<<<cdiv(nh, 256), 256>>>(nh);
        k_edge_max <<<cdiv(E, 256), 256>>>(E, H);
        k_z_init   <<<cdiv(nh, 256), 256>>>(nh);
        k_edge_exp <<<cdiv(E, 256), 256>>>(E, H);
        k_self_agg<1, 512><<<Nn, 128>>>(h, aggr);
        k_edge_agg<1, 512><<<E, 128>>>(h, aggr);
        k_bias_elu<<<cdiv(Nn * D, 256), 256>>>(aggr, b2, feat, Nn * D, D);
    }

    // ---------------- Layer 3: 512 -> 121, 1 head, mean (=identity) ------
    {
        const int H = 1, C = 121, D = 121;
        dim3 grid(cdiv(D, GBN), cdiv(Nn, GBM));
        k_gemm_tf32<<<grid, 256, GSMEM_BYTES>>>(feat, W3, h, Nn, D, 512);
        k_dots<<<Nn, 128>>>(h, a3s, a3d, Nn, H, C);
        int nh = Nn;
        k_self_init<<<cdiv(nh, 256), 256>>>(nh);
        k_edge_max <<<cdiv(E, 256), 256>>>(E, H);
        k_z_init   <<<cdiv(nh, 256), 256>>>(nh);
        k_edge_exp <<<cdiv(E, 256), 256>>>(E, H);
        k_self_agg<1, 121><<<Nn, 128>>>(h, out);   // overwrites poison
        k_edge_agg<1, 121><<<E, 128>>>(h, out);
        k_bias_add<<<cdiv(Nn * D, 256), 256>>>(out, b3, Nn * D, D);
    }
}

// round 3
// speedup vs baseline: 2.1361x; 1.9522x over previous
#include <cuda_runtime.h>
#include <cuda_bf16.h>
#include <math.h>

// ============================================================================
// Problem constants
// ============================================================================
#define NMAX   20000
#define EMAX   320000
#define DMAX   512
#define HMAX   8

// ============================================================================
// Scratch (static device globals)
// ============================================================================
__device__ int   g_src[EMAX];
__device__ int   g_dst[EMAX];
__device__ int   g_deg[NMAX];          // degree histogram
__device__ int   g_off[NMAX + 1];      // CSR offsets (by dst)
__device__ int   g_cur[NMAX];          // scatter cursor
__device__ int   g_csr_src[EMAX];      // src node per CSR slot
__device__ float g_h   [(size_t)NMAX * DMAX];
__device__ float g_feat[(size_t)NMAX * DMAX];
__device__ float g_als [NMAX * HMAX];
__device__ float g_ald [NMAX * HMAX];
__device__ float g_asf [NMAX * HMAX];  // normalized self-loop alpha
__device__ float g_ex  [(size_t)EMAX * HMAX]; // normalized alpha per CSR slot

// ============================================================================
// Helpers
// ============================================================================
__device__ __forceinline__ float lrelu(float x) { return x > 0.f ? x : 0.2f * x; }

__device__ __forceinline__ float tf32_rna(float x) {
    unsigned int r;
    asm("cvt.rna.tf32.f32 %0, %1;" : "=r"(r) : "f"(x));
    return __uint_as_float(r);
}

// ============================================================================
// Edge index conversion (int64 vs int32 runtime detect)
// ============================================================================
__global__ void k_convert(const unsigned int* __restrict__ w, int E) {
    bool is64 = true;
    #pragma unroll
    for (int i = 1; i < 64; i += 2) {
        if (w[i] != 0u) { is64 = false; break; }
    }
    int e = blockIdx.x * blockDim.x + threadIdx.x;
    if (e < E) {
        if (is64) {
            g_src[e] = (int)w[2 * e];
            g_dst[e] = (int)w[2 * (E + e)];
        } else {
            g_src[e] = (int)w[e];
            g_dst[e] = (int)w[E + e];
        }
    }
}

// ============================================================================
// CSR build: zero -> histogram -> scan -> scatter
// ============================================================================
__global__ void k_zero_deg(int Nn) {
    int i = blockIdx.x * blockDim.x + threadIdx.x;
    if (i < Nn) g_deg[i] = 0;
}

__global__ void k_hist(int E) {
    int e = blockIdx.x * blockDim.x + threadIdx.x;
    if (e < E) atomicAdd(&g_deg[g_dst[e]], 1);
}

__global__ void k_scan(int Nn, int E) {   // single block, 1024 threads
    __shared__ int sh[1024];
    __shared__ int s_carry;
    if (threadIdx.x == 0) s_carry = 0;
    __syncthreads();
    for (int base = 0; base < Nn; base += 1024) {
        int i = base + threadIdx.x;
        int v = (i < Nn) ? g_deg[i] : 0;
        sh[threadIdx.x] = v;
        __syncthreads();
        for (int o = 1; o < 1024; o <<= 1) {
            int t = (threadIdx.x >= o) ? sh[threadIdx.x - o] : 0;
            __syncthreads();
            sh[threadIdx.x] += t;
            __syncthreads();
        }
        int incl = sh[threadIdx.x];
        int excl = incl - v;
        if (i < Nn) {
            g_off[i] = s_carry + excl;
            g_cur[i] = s_carry + excl;
        }
        int total = sh[1023];
        __syncthreads();
        if (threadIdx.x == 0) s_carry += total;
        __syncthreads();
    }
    if (threadIdx.x == 0) g_off[Nn] = E;
}

__global__ void k_scatter(int E) {
    int e = blockIdx.x * blockDim.x + threadIdx.x;
    if (e < E) {
        int p = atomicAdd(&g_cur[g_dst[e]], 1);
        g_csr_src[p] = g_src[e];
    }
}

// ============================================================================
// 3xTF32 tensor-core GEMM (unchanged from R2)
// ============================================================================
#define GBM 128
#define GBN 64
#define GBK 16
#define BMp 132
#define BNp 68
#define ASZ (GBK * BMp)
#define BSZ (GBK * BNp)
#define GSMEM_BYTES ((4 * ASZ + 4 * BSZ) * 4)

__device__ __forceinline__ void mma_tf32(float c[4], const unsigned int a[4],
                                         const unsigned int b[2]) {
    asm volatile(
        "mma.sync.aligned.m16n8k8.row.col.f32.tf32.tf32.f32 "
        "{%0,%1,%2,%3}, {%4,%5,%6,%7}, {%8,%9}, {%0,%1,%2,%3};\n"
        : "+f"(c[0]), "+f"(c[1]), "+f"(c[2]), "+f"(c[3])
        : "r"(a[0]), "r"(a[1]), "r"(a[2]), "r"(a[3]), "r"(b[0]), "r"(b[1]));
}

__global__ __launch_bounds__(256, 2) void k_gemm_tf32(
    const float* __restrict__ A, const float* __restrict__ B,
    float* __restrict__ C, int M, int N, int K)
{
    extern __shared__ float s[];
    float* Ah = s;
    float* Al = s + 2 * ASZ;
    float* Bh = s + 4 * ASZ;
    float* Bl = s + 4 * ASZ + 2 * BSZ;

    const int tid  = threadIdx.x;
    const int lane = tid & 31, warp = tid >> 5;
    const int wm = warp >> 1, wn = warp & 1;
    const int g = lane >> 2, tq = lane & 3;
    const int row0 = blockIdx.y * GBM;
    const int col0 = blockIdx.x * GBN;
    const int arow = tid >> 1;
    const int akb  = (tid & 1) * 8;

    float c[2][4][4];
    #pragma unroll
    for (int i = 0; i < 2; i++)
        #pragma unroll
        for (int j = 0; j < 4; j++)
            #pragma unroll
            for (int q = 0; q < 4; q++) c[i][j][q] = 0.f;

    const int nIt = (K + GBK - 1) / GBK;
    float ra[8], rb[4];

    {
        #pragma unroll
        for (int j = 0; j < 8; j++) {
            int gk = akb + j;
            ra[j] = (row0 + arow < M && gk < K)
                    ? A[(size_t)(row0 + arow) * K + gk] : 0.f;
        }
        #pragma unroll
        for (int p = 0; p < 4; p++) {
            int e = tid + p * 256, bk = e >> 6, bn = e & 63;
            rb[p] = (bk < K && col0 + bn < N)
                    ? B[(size_t)bk * N + col0 + bn] : 0.f;
        }
    }
    {
        #pragma unroll
        for (int j = 0; j < 8; j++) {
            float v = ra[j], h = tf32_rna(v), l = tf32_rna(v - h);
            int off = (akb + j) * BMp + arow;
            Ah[off] = h; Al[off] = l;
        }
        #pragma unroll
        for (int p = 0; p < 4; p++) {
            int e = tid + p * 256, bk = e >> 6, bn = e & 63;
            float v = rb[p], h = tf32_rna(v), l = tf32_rna(v - h);
            int off = bk * BNp + bn;
            Bh[off] = h; Bl[off] = l;
        }
    }
    __syncthreads();

    for (int it = 0; it < nIt; it++) {
        if (it + 1 < nIt) {
            int k0 = (it + 1) * GBK;
            #pragma unroll
            for (int j = 0; j < 8; j++) {
                int gk = k0 + akb + j;
                ra[j] = (row0 + arow < M && gk < K)
                        ? A[(size_t)(row0 + arow) * K + gk] : 0.f;
            }
            #pragma unroll
            for (int p = 0; p < 4; p++) {
                int e = tid + p * 256, bk = e >> 6, bn = e & 63;
                int gk = k0 + bk;
                rb[p] = (gk < K && col0 + bn < N)
                        ? B[(size_t)gk * N + col0 + bn] : 0.f;
            }
        }

        const int buf = it & 1;
        const float* ah_ = Ah + buf * ASZ;
        const float* al_ = Al + buf * ASZ;
        const float* bh_ = Bh + buf * BSZ;
        const float* bl_ = Bl + buf * BSZ;

        #pragma unroll
        for (int ks = 0; ks < 2; ks++) {
            const int kb = ks * 8;
            unsigned int afh[2][4], afl[2][4];
            #pragma unroll
            for (int tm = 0; tm < 2; tm++) {
                int m  = wm * 32 + tm * 16 + g;
                int o1 = (kb + tq) * BMp + m;
                int o2 = (kb + tq + 4) * BMp + m;
                afh[tm][0] = __float_as_uint(ah_[o1]);
                afh[tm][1] = __float_as_uint(ah_[o1 + 8]);
                afh[tm][2] = __float_as_uint(ah_[o2]);
                afh[tm][3] = __float_as_uint(ah_[o2 + 8]);
                afl[tm][0] = __float_as_uint(al_[o1]);
                afl[tm][1] = __float_as_uint(al_[o1 + 8]);
                afl[tm][2] = __float_as_uint(al_[o2]);
                afl[tm][3] = __float_as_uint(al_[o2 + 8]);
            }
            unsigned int bfh[4][2], bfl[4][2];
            #pragma unroll
            for (int tn = 0; tn < 4; tn++) {
                int n  = wn * 32 + tn * 8 + g;
                int o1 = (kb + tq) * BNp + n;
                int o2 = (kb + tq + 4) * BNp + n;
                bfh[tn][0] = __float_as_uint(bh_[o1]);
                bfh[tn][1] = __float_as_uint(bh_[o2]);
                bfl[tn][0] = __float_as_uint(bl_[o1]);
                bfl[tn][1] = __float_as_uint(bl_[o2]);
            }
            #pragma unroll
            for (int tm = 0; tm < 2; tm++)
                #pragma unroll
                for (int tn = 0; tn < 4; tn++) {
                    mma_tf32(c[tm][tn], afh[tm], bfh[tn]);
                    mma_tf32(c[tm][tn], afh[tm], bfl[tn]);
                    mma_tf32(c[tm][tn], afl[tm], bfh[tn]);
                }
        }

        if (it + 1 < nIt) {
            int nb = buf ^ 1;
            float* ahd = Ah + nb * ASZ;
            float* ald = Al + nb * ASZ;
            float* bhd = Bh + nb * BSZ;
            float* bld = Bl + nb * BSZ;
            #pragma unroll
            for (int j = 0; j < 8; j++) {
                float v = ra[j], h = tf32_rna(v), l = tf32_rna(v - h);
                int off = (akb + j) * BMp + arow;
                ahd[off] = h; ald[off] = l;
            }
            #pragma unroll
            for (int p = 0; p < 4; p++) {
                int e = tid + p * 256, bk = e >> 6, bn = e & 63;
                float v = rb[p], h = tf32_rna(v), l = tf32_rna(v - h);
                int off = bk * BNp + bn;
                bhd[off] = h; bld[off] = l;
            }
            __syncthreads();
        }
    }

    #pragma unroll
    for (int tm = 0; tm < 2; tm++) {
        #pragma unroll
        for (int tn = 0; tn < 4; tn++) {
            int gm0 = row0 + wm * 32 + tm * 16 + g;
            int gn0 = col0 + wn * 32 + tn * 8 + 2 * tq;
            if (gm0 < M) {
                if (gn0 < N)     C[(size_t)gm0 * N + gn0]     = c[tm][tn][0];
                if (gn0 + 1 < N) C[(size_t)gm0 * N + gn0 + 1] = c[tm][tn][1];
            }
            if (gm0 + 8 < M) {
                if (gn0 < N)     C[(size_t)(gm0 + 8) * N + gn0]     = c[tm][tn][2];
                if (gn0 + 1 < N) C[(size_t)(gm0 + 8) * N + gn0 + 1] = c[tm][tn][3];
            }
        }
    }
}

// ============================================================================
// Attention scalar dots
// ============================================================================
__global__ void k_dots(const float* __restrict__ h,
                       const float* __restrict__ asrc,
                       const float* __restrict__ adst,
                       int Nn, int H, int C)
{
    int n = blockIdx.x;
    if (n >= Nn) return;
    __shared__ float sh[64];
    const int D = H * C;
    for (int hh = 0; hh < H; hh++) {
        float ls = 0.f, ld = 0.f;
        for (int c = threadIdx.x; c < C; c += blockDim.x) {
            float v = h[(size_t)n * D + hh * C + c];
            ls = fmaf(v, asrc[hh * C + c], ls);
            ld = fmaf(v, adst[hh * C + c], ld);
        }
        #pragma unroll
        for (int o = 16; o > 0; o >>= 1) {
            ls += __shfl_down_sync(0xffffffffu, ls, o);
            ld += __shfl_down_sync(0xffffffffu, ld, o);
        }
        int lane = threadIdx.x & 31, wid = threadIdx.x >> 5;
        if (lane == 0) { sh[wid] = ls; sh[32 + wid] = ld; }
        __syncthreads();
        if (threadIdx.x == 0) {
            float a = 0.f, b = 0.f;
            int nw = blockDim.x >> 5;
            for (int i = 0; i < nw; i++) { a += sh[i]; b += sh[32 + i]; }
            g_als[n * H + hh] = a;
            g_ald[n * H + hh] = b;
        }
        __syncthreads();
    }
}

// ============================================================================
// Fused CSR edge-softmax: one warp per (node, head). Writes NORMALIZED alpha
// for every in-edge (g_ex, CSR order) and the self-loop (g_asf). No atomics.
// ============================================================================
template <int H>
__global__ void k_softmax_csr(int Nn) {
    const int warp = threadIdx.x >> 5;
    const int lane = threadIdx.x & 31;
    int t, hh;
    if (H == 8) { t = blockIdx.x; hh = warp; }
    else        { t = blockIdx.x * 8 + warp; hh = 0; }
    if (t >= Nn) return;

    const int beg = g_off[t], end = g_off[t + 1];
    const float ald_t = g_ald[t * H + hh];
    const float es = lrelu(g_als[t * H + hh] + ald_t);   // self-loop logit

    float m = es;
    for (int p = beg + lane; p < end; p += 32) {
        int s = g_csr_src[p];
        m = fmaxf(m, lrelu(g_als[s * H + hh] + ald_t));
    }
    #pragma unroll
    for (int o = 16; o > 0; o >>= 1)
        m = fmaxf(m, __shfl_xor_sync(0xffffffffu, m, o));

    float z = 0.f;
    for (int p = beg + lane; p < end; p += 32) {
        int s = g_csr_src[p];
        float v = lrelu(g_als[s * H + hh] + ald_t);
        float ex = expf(v - m);
        g_ex[(size_t)p * H + hh] = ex;
        z += ex;
    }
    #pragma unroll
    for (int o = 16; o > 0; o >>= 1)
        z += __shfl_xor_sync(0xffffffffu, z, o);

    float exs = expf(es - m);
    float rz  = 1.f / (z + exs + 1e-16f);
    if (lane == 0) g_asf[t * H + hh] = exs * rz;
    for (int p = beg + lane; p < end; p += 32)
        g_ex[(size_t)p * H + hh] *= rz;
}

// ============================================================================
// Gather-side aggregation + fused bias (+ELU). Block per node, float4/thread.
// ============================================================================
template <int H, int C>
__global__ void k_agg_csr(const float* __restrict__ h,
                          const float* __restrict__ bias,
                          float* __restrict__ outp, int Nn, int do_elu) {
    constexpr int D = H * C;          // 512, blockDim = 128
    const int t  = blockIdx.x;
    const int c4 = threadIdx.x * 4;
    const int hh = c4 / C;

    float a = g_asf[t * H + hh];
    float4 hv = *(const float4*)&h[(size_t)t * D + c4];
    float4 acc = make_float4(a * hv.x, a * hv.y, a * hv.z, a * hv.w);

    const int beg = g_off[t], end = g_off[t + 1];
    for (int p = beg; p < end; p++) {
        int s = g_csr_src[p];
        float al = g_ex[(size_t)p * H + hh];
        float4 v = *(const float4*)&h[(size_t)s * D + c4];
        acc.x = fmaf(al, v.x, acc.x);
        acc.y = fmaf(al, v.y, acc.y);
        acc.z = fmaf(al, v.z, acc.z);
        acc.w = fmaf(al, v.w, acc.w);
    }
    float4 b = *(const float4*)&bias[c4];
    acc.x += b.x; acc.y += b.y; acc.z += b.z; acc.w += b.w;
    if (do_elu) {
        acc.x = acc.x > 0.f ? acc.x : expf(acc.x) - 1.f;
        acc.y = acc.y > 0.f ? acc.y : expf(acc.y) - 1.f;
        acc.z = acc.z > 0.f ? acc.z : expf(acc.z) - 1.f;
        acc.w = acc.w > 0.f ? acc.w : expf(acc.w) - 1.f;
    }
    *(float4*)&outp[(size_t)t * D + c4] = acc;
}

// Scalar variant for D=121 (layer 3, bias only, no ELU)
__global__ void k_agg_csr_s(const float* __restrict__ h,
                            const float* __restrict__ bias,
                            float* __restrict__ outp, int Nn, int D) {
    const int t = blockIdx.x;
    const int c = threadIdx.x;
    if (c >= D) return;
    float acc = g_asf[t] * h[(size_t)t * D + c];
    const int beg = g_off[t], end = g_off[t + 1];
    for (int p = beg; p < end; p++) {
        int s = g_csr_src[p];
        acc = fmaf(g_ex[p], h[(size_t)s * D + c], acc);
    }
    outp[(size_t)t * D + c] = acc + bias[c];
}

// ============================================================================
// Host launch
// ============================================================================
static inline int cdiv(int a, int b) { return (a + b - 1) / b; }

extern "C" void kernel_launch(void* const* d_in, const int* in_sizes, int n_in,
                              void* d_out, int out_size) {
    const float* x   = (const float*)d_in[0];
    const void*  ei  = d_in[1];
    const float* W1  = (const float*)d_in[2];
    const float* a1s = (const float*)d_in[3];
    const float* a1d = (const float*)d_in[4];
    const float* b1  = (const float*)d_in[5];
    const float* W2  = (const float*)d_in[6];
    const float* a2s = (const float*)d_in[7];
    const float* a2d = (const float*)d_in[8];
    const float* b2  = (const float*)d_in[9];
    const float* W3  = (const float*)d_in[10];
    const float* a3s = (const float*)d_in[11];
    const float* a3d = (const float*)d_in[12];
    const float* b3  = (const float*)d_in[13];
    float* out = (float*)d_out;

    const int Nn = in_sizes[0] / 50;   // 20000
    const int E  = in_sizes[1] / 2;    // 320000

    float *h, *feat;
    cudaGetSymbolAddress((void**)&h,    g_h);
    cudaGetSymbolAddress((void**)&feat, g_feat);

    cudaFuncSetAttribute(k_gemm_tf32,
                         cudaFuncAttributeMaxDynamicSharedMemorySize, GSMEM_BYTES);

    // ---- graph preprocessing (per launch; edges identical across layers) ----
    k_convert <<<cdiv(E, 256), 256>>>((const unsigned int*)ei, E);
    k_zero_deg<<<cdiv(Nn, 256), 256>>>(Nn);
    k_hist    <<<cdiv(E, 256), 256>>>(E);
    k_scan    <<<1, 1024>>>(Nn, E);
    k_scatter <<<cdiv(E, 256), 256>>>(E);

    // ---------------- Layer 1: 50 -> 8 heads x 64, concat ----------------
    {
        dim3 grid(cdiv(512, GBN), cdiv(Nn, GBM));
        k_gemm_tf32<<<grid, 256, GSMEM_BYTES>>>(x, W1, h, Nn, 512, 50);
        k_dots<<<Nn, 128>>>(h, a1s, a1d, Nn, 8, 64);
        k_softmax_csr<8><<<Nn, 256>>>(Nn);
        k_agg_csr<8, 64><<<Nn, 128>>>(h, b1, feat, Nn, 1);
    }

    // ---------------- Layer 2: 512 -> 512, 1 head ----------------
    {
        dim3 grid(cdiv(512, GBN), cdiv(Nn, GBM));
        k_gemm_tf32<<<grid, 256, GSMEM_BYTES>>>(feat, W2, h, Nn, 512, 512);
        k_dots<<<Nn, 128>>>(h, a2s, a2d, Nn, 1, 512);
        k_softmax_csr<1><<<cdiv(Nn, 8), 256>>>(Nn);
        k_agg_csr<1, 512><<<Nn, 128>>>(h, b2, feat, Nn, 1);
    }

    // ---------------- Layer 3: 512 -> 121, 1 head, mean (=identity) ------
    {
        dim3 grid(cdiv(121, GBN), cdiv(Nn, GBM));
        k_gemm_tf32<<<grid, 256, GSMEM_BYTES>>>(feat, W3, h, Nn, 121, 512);
        k_dots<<<Nn, 128>>>(h, a3s, a3d, Nn, 1, 121);
        k_softmax_csr<1><<<cdiv(Nn, 8), 256>>>(Nn);
        k_agg_csr_s<<<Nn, 128>>>(h, b3, out, Nn, 121);
    }
}

// round 4
// speedup vs baseline: 2.3365x; 1.0938x over previous
#include <cuda_runtime.h>
#include <cuda_bf16.h>
#include <math.h>

// ============================================================================
// Problem constants
// ============================================================================
#define NMAX   20000
#define EMAX   320000
#define DMAX   512
#define HMAX   8

// ============================================================================
// Scratch (static device globals)
// ============================================================================
__device__ int   g_src[EMAX];
__device__ int   g_dst[EMAX];
__device__ int   g_deg[NMAX];
__device__ int   g_off[NMAX + 1];
__device__ int   g_cur[NMAX];
__device__ int   g_csr_src[EMAX];
__device__ float g_h   [(size_t)NMAX * DMAX];
__device__ float g_feat[(size_t)NMAX * DMAX];
__device__ float g_als [NMAX * HMAX];
__device__ float g_ald [NMAX * HMAX];
__device__ float g_asf [NMAX * HMAX];
__device__ float g_ex  [(size_t)EMAX * HMAX];

// ============================================================================
// Helpers
// ============================================================================
__device__ __forceinline__ float lrelu(float x) { return x > 0.f ? x : 0.2f * x; }

__device__ __forceinline__ float tf32_rna(float x) {
    unsigned int r;
    asm("cvt.rna.tf32.f32 %0, %1;" : "=r"(r) : "f"(x));
    return __uint_as_float(r);
}

// ============================================================================
// Preprocessing
// ============================================================================
__global__ void k_zero_deg(int Nn) {
    int i = blockIdx.x * blockDim.x + threadIdx.x;
    if (i < Nn) g_deg[i] = 0;
}

// convert edge index (runtime int64/int32 detect) + degree histogram fused
__global__ void k_convert_hist(const unsigned int* __restrict__ w, int E) {
    bool is64 = true;
    #pragma unroll
    for (int i = 1; i < 64; i += 2) {
        if (w[i] != 0u) { is64 = false; break; }
    }
    int e = blockIdx.x * blockDim.x + threadIdx.x;
    if (e < E) {
        int s, d;
        if (is64) { s = (int)w[2 * e]; d = (int)w[2 * (E + e)]; }
        else      { s = (int)w[e];     d = (int)w[E + e]; }
        g_src[e] = s;
        g_dst[e] = d;
        atomicAdd(&g_deg[d], 1);
    }
}

// single-block scan: thread-serial chunks + warp/block scan of partials
__global__ void k_scan(int Nn, int E) {
    __shared__ int wsum[32];
    const int T = 1024;
    const int tid  = threadIdx.x;
    const int lane = tid & 31, w = tid >> 5;
    const int CH = (Nn + T - 1) / T;
    int base = tid * CH;
    int lim  = Nn - base;
    if (lim < 0) lim = 0;
    if (lim > CH) lim = CH;

    int sum = 0;
    for (int j = 0; j < lim; j++) sum += g_deg[base + j];

    int v = sum;
    #pragma unroll
    for (int o = 1; o < 32; o <<= 1) {
        int t = __shfl_up_sync(0xffffffffu, v, o);
        if (lane >= o) v += t;
    }
    if (lane == 31) wsum[w] = v;
    __syncthreads();
    if (w == 0) {
        int s = wsum[lane];
        #pragma unroll
        for (int o = 1; o < 32; o <<= 1) {
            int t = __shfl_up_sync(0xffffffffu, s, o);
            if (lane >= o) s += t;
        }
        wsum[lane] = s;
    }
    __syncthreads();
    int run = v - sum + (w > 0 ? wsum[w - 1] : 0);   // exclusive prefix
    for (int j = 0; j < lim; j++) {
        g_off[base + j] = run;
        g_cur[base + j] = run;
        run += g_deg[base + j];
    }
    if (tid == 0) g_off[Nn] = E;
}

__global__ void k_scatter(int E) {
    int e = blockIdx.x * blockDim.x + threadIdx.x;
    if (e < E) {
        int p = atomicAdd(&g_cur[g_dst[e]], 1);
        g_csr_src[p] = g_src[e];
    }
}

__global__ void k_zero_dots(int total) {
    int i = blockIdx.x * blockDim.x + threadIdx.x;
    if (i < total) { g_als[i] = 0.f; g_ald[i] = 0.f; }
}

// ============================================================================
// 3xTF32 tensor-core GEMM with fused attention-dot epilogue.
// C[M,N] = A[M,K] @ B[K,N]; epilogue accumulates als/ald = C . asrc/adst
// (per row, per head) via quad-shuffle reduction + atomicAdd.
// ============================================================================
#define GBM 128
#define GBN 64
#define GBK 16
#define BMp 132
#define BNp 68
#define ASZ (GBK * BMp)
#define BSZ (GBK * BNp)
#define GSMEM_BYTES ((4 * ASZ + 4 * BSZ) * 4)

__device__ __forceinline__ void mma_tf32(float c[4], const unsigned int a[4],
                                         const unsigned int b[2]) {
    asm volatile(
        "mma.sync.aligned.m16n8k8.row.col.f32.tf32.tf32.f32 "
        "{%0,%1,%2,%3}, {%4,%5,%6,%7}, {%8,%9}, {%0,%1,%2,%3};\n"
        : "+f"(c[0]), "+f"(c[1]), "+f"(c[2]), "+f"(c[3])
        : "r"(a[0]), "r"(a[1]), "r"(a[2]), "r"(a[3]), "r"(b[0]), "r"(b[1]));
}

__global__ __launch_bounds__(256, 2) void k_gemm_tf32(
    const float* __restrict__ A, const float* __restrict__ B,
    float* __restrict__ C, int M, int N, int K,
    const float* __restrict__ asrc, const float* __restrict__ adst,
    int H, int Chead)
{
    extern __shared__ float s[];
    float* Ah = s;
    float* Al = s + 2 * ASZ;
    float* Bh = s + 4 * ASZ;
    float* Bl = s + 4 * ASZ + 2 * BSZ;

    const int tid  = threadIdx.x;
    const int lane = tid & 31, warp = tid >> 5;
    const int wm = warp >> 1, wn = warp & 1;
    const int g = lane >> 2, tq = lane & 3;
    const int row0 = blockIdx.y * GBM;
    const int col0 = blockIdx.x * GBN;
    const int arow = tid >> 1;
    const int akb  = (tid & 1) * 8;

    float c[2][4][4];
    #pragma unroll
    for (int i = 0; i < 2; i++)
        #pragma unroll
        for (int j = 0; j < 4; j++)
            #pragma unroll
            for (int q = 0; q < 4; q++) c[i][j][q] = 0.f;

    const int nIt = (K + GBK - 1) / GBK;
    float ra[8], rb[4];

    {
        #pragma unroll
        for (int j = 0; j < 8; j++) {
            int gk = akb + j;
            ra[j] = (row0 + arow < M && gk < K)
                    ? A[(size_t)(row0 + arow) * K + gk] : 0.f;
        }
        #pragma unroll
        for (int p = 0; p < 4; p++) {
            int e = tid + p * 256, bk = e >> 6, bn = e & 63;
            rb[p] = (bk < K && col0 + bn < N)
                    ? B[(size_t)bk * N + col0 + bn] : 0.f;
        }
    }
    {
        #pragma unroll
        for (int j = 0; j < 8; j++) {
            float v = ra[j], h = tf32_rna(v), l = tf32_rna(v - h);
            int off = (akb + j) * BMp + arow;
            Ah[off] = h; Al[off] = l;
        }
        #pragma unroll
        for (int p = 0; p < 4; p++) {
            int e = tid + p * 256, bk = e >> 6, bn = e & 63;
            float v = rb[p], h = tf32_rna(v), l = tf32_rna(v - h);
            int off = bk * BNp + bn;
            Bh[off] = h; Bl[off] = l;
        }
    }
    __syncthreads();

    for (int it = 0; it < nIt; it++) {
        if (it + 1 < nIt) {
            int k0 = (it + 1) * GBK;
            #pragma unroll
            for (int j = 0; j < 8; j++) {
                int gk = k0 + akb + j;
                ra[j] = (row0 + arow < M && gk < K)
                        ? A[(size_t)(row0 + arow) * K + gk] : 0.f;
            }
            #pragma unroll
            for (int p = 0; p < 4; p++) {
                int e = tid + p * 256, bk = e >> 6, bn = e & 63;
                int gk = k0 + bk;
                rb[p] = (gk < K && col0 + bn < N)
                        ? B[(size_t)gk * N + col0 + bn] : 0.f;
            }
        }

        const int buf = it & 1;
        const float* ah_ = Ah + buf * ASZ;
        const float* al_ = Al + buf * ASZ;
        const float* bh_ = Bh + buf * BSZ;
        const float* bl_ = Bl + buf * BSZ;

        #pragma unroll
        for (int ks = 0; ks < 2; ks++) {
            const int kb = ks * 8;
            unsigned int afh[2][4], afl[2][4];
            #pragma unroll
            for (int tm = 0; tm < 2; tm++) {
                int m  = wm * 32 + tm * 16 + g;
                int o1 = (kb + tq) * BMp + m;
                int o2 = (kb + tq + 4) * BMp + m;
                afh[tm][0] = __float_as_uint(ah_[o1]);
                afh[tm][1] = __float_as_uint(ah_[o1 + 8]);
                afh[tm][2] = __float_as_uint(ah_[o2]);
                afh[tm][3] = __float_as_uint(ah_[o2 + 8]);
                afl[tm][0] = __float_as_uint(al_[o1]);
                afl[tm][1] = __float_as_uint(al_[o1 + 8]);
                afl[tm][2] = __float_as_uint(al_[o2]);
                afl[tm][3] = __float_as_uint(al_[o2 + 8]);
            }
            unsigned int bfh[4][2], bfl[4][2];
            #pragma unroll
            for (int tn = 0; tn < 4; tn++) {
                int n  = wn * 32 + tn * 8 + g;
                int o1 = (kb + tq) * BNp + n;
                int o2 = (kb + tq + 4) * BNp + n;
                bfh[tn][0] = __float_as_uint(bh_[o1]);
                bfh[tn][1] = __float_as_uint(bh_[o2]);
                bfl[tn][0] = __float_as_uint(bl_[o1]);
                bfl[tn][1] = __float_as_uint(bl_[o2]);
            }
            #pragma unroll
            for (int tm = 0; tm < 2; tm++)
                #pragma unroll
                for (int tn = 0; tn < 4; tn++) {
                    mma_tf32(c[tm][tn], afh[tm], bfh[tn]);
                    mma_tf32(c[tm][tn], afh[tm], bfl[tn]);
                    mma_tf32(c[tm][tn], afl[tm], bfh[tn]);
                }
        }

        if (it + 1 < nIt) {
            int nb = buf ^ 1;
            float* ahd = Ah + nb * ASZ;
            float* ald = Al + nb * ASZ;
            float* bhd = Bh + nb * BSZ;
            float* bld = Bl + nb * BSZ;
            #pragma unroll
            for (int j = 0; j < 8; j++) {
                float v = ra[j], h = tf32_rna(v), l = tf32_rna(v - h);
                int off = (akb + j) * BMp + arow;
                ahd[off] = h; ald[off] = l;
            }
            #pragma unroll
            for (int p = 0; p < 4; p++) {
                int e = tid + p * 256, bk = e >> 6, bn = e & 63;
                float v = rb[p], h = tf32_rna(v), l = tf32_rna(v - h);
                int off = bk * BNp + bn;
                bhd[off] = h; bld[off] = l;
            }
            __syncthreads();
        }
    }

    // ---- epilogue: store C + fused attention dots ----
    const int hh = col0 / Chead;
    #pragma unroll
    for (int tm = 0; tm < 2; tm++) {
        float l0s = 0.f, l0d = 0.f, l1s = 0.f, l1d = 0.f;
        #pragma unroll
        for (int tn = 0; tn < 4; tn++) {
            int gm0 = row0 + wm * 32 + tm * 16 + g;
            int gn0 = col0 + wn * 32 + tn * 8 + 2 * tq;
            float as0 = (gn0 < N)     ? asrc[gn0]     : 0.f;
            float ad0 = (gn0 < N)     ? adst[gn0]     : 0.f;
            float as1 = (gn0 + 1 < N) ? asrc[gn0 + 1] : 0.f;
            float ad1 = (gn0 + 1 < N) ? adst[gn0 + 1] : 0.f;

            l0s = fmaf(c[tm][tn][0], as0, fmaf(c[tm][tn][1], as1, l0s));
            l0d = fmaf(c[tm][tn][0], ad0, fmaf(c[tm][tn][1], ad1, l0d));
            l1s = fmaf(c[tm][tn][2], as0, fmaf(c[tm][tn][3], as1, l1s));
            l1d = fmaf(c[tm][tn][2], ad0, fmaf(c[tm][tn][3], ad1, l1d));

            if (gm0 < M) {
                if (gn0 < N)     C[(size_t)gm0 * N + gn0]     = c[tm][tn][0];
                if (gn0 + 1 < N) C[(size_t)gm0 * N + gn0 + 1] = c[tm][tn][1];
            }
            if (gm0 + 8 < M) {
                if (gn0 < N)     C[(size_t)(gm0 + 8) * N + gn0]     = c[tm][tn][2];
                if (gn0 + 1 < N) C[(size_t)(gm0 + 8) * N + gn0 + 1] = c[tm][tn][3];
            }
        }
        // reduce over the 4 quad lanes (tq = lane bits 0..1) owning each row
        #pragma unroll
        for (int o = 1; o <= 2; o <<= 1) {
            l0s += __shfl_xor_sync(0xffffffffu, l0s, o);
            l0d += __shfl_xor_sync(0xffffffffu, l0d, o);
            l1s += __shfl_xor_sync(0xffffffffu, l1s, o);
            l1d += __shfl_xor_sync(0xffffffffu, l1d, o);
        }
        if (tq == 0) {
            int r0 = row0 + wm * 32 + tm * 16 + g;
            if (r0 < M) {
                atomicAdd(&g_als[r0 * H + hh], l0s);
                atomicAdd(&g_ald[r0 * H + hh], l0d);
            }
            if (r0 + 8 < M) {
                atomicAdd(&g_als[(r0 + 8) * H + hh], l1s);
                atomicAdd(&g_ald[(r0 + 8) * H + hh], l1d);
            }
        }
    }
}

// ============================================================================
// Fused CSR edge-softmax: one warp per (node, head). No atomics.
// ============================================================================
template <int H>
__global__ void k_softmax_csr(int Nn) {
    const int warp = threadIdx.x >> 5;
    const int lane = threadIdx.x & 31;
    int t, hh;
    if (H == 8) { t = blockIdx.x; hh = warp; }
    else        { t = blockIdx.x * 8 + warp; hh = 0; }
    if (t >= Nn) return;

    const int beg = g_off[t], end = g_off[t + 1];
    const float ald_t = g_ald[t * H + hh];
    const float es = lrelu(g_als[t * H + hh] + ald_t);

    float m = es;
    for (int p = beg + lane; p < end; p += 32) {
        int s = g_csr_src[p];
        m = fmaxf(m, lrelu(g_als[s * H + hh] + ald_t));
    }
    #pragma unroll
    for (int o = 16; o > 0; o >>= 1)
        m = fmaxf(m, __shfl_xor_sync(0xffffffffu, m, o));

    float z = 0.f;
    for (int p = beg + lane; p < end; p += 32) {
        int s = g_csr_src[p];
        float v = lrelu(g_als[s * H + hh] + ald_t);
        float ex = expf(v - m);
        g_ex[(size_t)p * H + hh] = ex;
        z += ex;
    }
    #pragma unroll
    for (int o = 16; o > 0; o >>= 1)
        z += __shfl_xor_sync(0xffffffffu, z, o);

    float exs = expf(es - m);
    float rz  = 1.f / (z + exs + 1e-16f);
    if (lane == 0) g_asf[t * H + hh] = exs * rz;
    for (int p = beg + lane; p < end; p += 32)
        g_ex[(size_t)p * H + hh] *= rz;
}

// ============================================================================
// Gather-side aggregation + fused bias (+ELU). Block per node, float4/thread.
// Loop unrolled x2 for MLP.
// ============================================================================
template <int H, int C>
__global__ void k_agg_csr(const float* __restrict__ h,
                          const float* __restrict__ bias,
                          float* __restrict__ outp, int Nn, int do_elu) {
    constexpr int D = H * C;          // 512, blockDim = 128
    const int t  = blockIdx.x;
    const int c4 = threadIdx.x * 4;
    const int hh = c4 / C;

    float a = g_asf[t * H + hh];
    float4 hv = *(const float4*)&h[(size_t)t * D + c4];
    float4 acc = make_float4(a * hv.x, a * hv.y, a * hv.z, a * hv.w);

    const int beg = g_off[t], end = g_off[t + 1];
    int p = beg;
    for (; p + 1 < end; p += 2) {
        int s0 = g_csr_src[p];
        int s1 = g_csr_src[p + 1];
        float a0 = g_ex[(size_t)p * H + hh];
        float a1 = g_ex[(size_t)(p + 1) * H + hh];
        float4 v0 = *(const float4*)&h[(size_t)s0 * D + c4];
        float4 v1 = *(const float4*)&h[(size_t)s1 * D + c4];
        acc.x = fmaf(a0, v0.x, acc.x); acc.y = fmaf(a0, v0.y, acc.y);
        acc.z = fmaf(a0, v0.z, acc.z); acc.w = fmaf(a0, v0.w, acc.w);
        acc.x = fmaf(a1, v1.x, acc.x); acc.y = fmaf(a1, v1.y, acc.y);
        acc.z = fmaf(a1, v1.z, acc.z); acc.w = fmaf(a1, v1.w, acc.w);
    }
    if (p < end) {
        int s0 = g_csr_src[p];
        float a0 = g_ex[(size_t)p * H + hh];
        float4 v0 = *(const float4*)&h[(size_t)s0 * D + c4];
        acc.x = fmaf(a0, v0.x, acc.x); acc.y = fmaf(a0, v0.y, acc.y);
        acc.z = fmaf(a0, v0.z, acc.z); acc.w = fmaf(a0, v0.w, acc.w);
    }
    float4 b = *(const float4*)&bias[c4];
    acc.x += b.x; acc.y += b.y; acc.z += b.z; acc.w += b.w;
    if (do_elu) {
        acc.x = acc.x > 0.f ? acc.x : expf(acc.x) - 1.f;
        acc.y = acc.y > 0.f ? acc.y : expf(acc.y) - 1.f;
        acc.z = acc.z > 0.f ? acc.z : expf(acc.z) - 1.f;
        acc.w = acc.w > 0.f ? acc.w : expf(acc.w) - 1.f;
    }
    *(float4*)&outp[(size_t)t * D + c4] = acc;
}

// Scalar variant for D=121 (layer 3, bias only, no ELU)
__global__ void k_agg_csr_s(const float* __restrict__ h,
                            const float* __restrict__ bias,
                            float* __restrict__ outp, int Nn, int D) {
    const int t = blockIdx.x;
    const int c = threadIdx.x;
    if (c >= D) return;
    float acc = g_asf[t] * h[(size_t)t * D + c];
    const int beg = g_off[t], end = g_off[t + 1];
    int p = beg;
    for (; p + 1 < end; p += 2) {
        int s0 = g_csr_src[p], s1 = g_csr_src[p + 1];
        float a0 = g_ex[p], a1 = g_ex[p + 1];
        float v0 = h[(size_t)s0 * D + c];
        float v1 = h[(size_t)s1 * D + c];
        acc = fmaf(a0, v0, acc);
        acc = fmaf(a1, v1, acc);
    }
    if (p < end)
        acc = fmaf(g_ex[p], h[(size_t)g_csr_src[p] * D + c], acc);
    outp[(size_t)t * D + c] = acc + bias[c];
}

// ============================================================================
// Host launch
// ============================================================================
static inline int cdiv(int a, int b) { return (a + b - 1) / b; }

extern "C" void kernel_launch(void* const* d_in, const int* in_sizes, int n_in,
                              void* d_out, int out_size) {
    const float* x   = (const float*)d_in[0];
    const void*  ei  = d_in[1];
    const float* W1  = (const float*)d_in[2];
    const float* a1s = (const float*)d_in[3];
    const float* a1d = (const float*)d_in[4];
    const float* b1  = (const float*)d_in[5];
    const float* W2  = (const float*)d_in[6];
    const float* a2s = (const float*)d_in[7];
    const float* a2d = (const float*)d_in[8];
    const float* b2  = (const float*)d_in[9];
    const float* W3  = (const float*)d_in[10];
    const float* a3s = (const float*)d_in[11];
    const float* a3d = (const float*)d_in[12];
    const float* b3  = (const float*)d_in[13];
    float* out = (float*)d_out;

    const int Nn = in_sizes[0] / 50;   // 20000
    const int E  = in_sizes[1] / 2;    // 320000

    float *h, *feat;
    cudaGetSymbolAddress((void**)&h,    g_h);
    cudaGetSymbolAddress((void**)&feat, g_feat);

    cudaFuncSetAttribute(k_gemm_tf32,
                         cudaFuncAttributeMaxDynamicSharedMemorySize, GSMEM_BYTES);

    // ---- graph preprocessing ----
    k_zero_deg    <<<cdiv(Nn, 256), 256>>>(Nn);
    k_convert_hist<<<cdiv(E, 256), 256>>>((const unsigned int*)ei, E);
    k_scan        <<<1, 1024>>>(Nn, E);
    k_scatter     <<<cdiv(E, 256), 256>>>(E);

    // ---------------- Layer 1: 50 -> 8 heads x 64, concat ----------------
    {
        k_zero_dots<<<cdiv(Nn * 8, 256), 256>>>(Nn * 8);
        dim3 grid(cdiv(512, GBN), cdiv(Nn, GBM));
        k_gemm_tf32<<<grid, 256, GSMEM_BYTES>>>(x, W1, h, Nn, 512, 50,
                                                a1s, a1d, 8, 64);
        k_softmax_csr<8><<<Nn, 256>>>(Nn);
        k_agg_csr<8, 64><<<Nn, 128>>>(h, b1, feat, Nn, 1);
    }

    // ---------------- Layer 2: 512 -> 512, 1 head ----------------
    {
        k_zero_dots<<<cdiv(Nn, 256), 256>>>(Nn);
        dim3 grid(cdiv(512, GBN), cdiv(Nn, GBM));
        k_gemm_tf32<<<grid, 256, GSMEM_BYTES>>>(feat, W2, h, Nn, 512, 512,
                                                a2s, a2d, 1, 512);
        k_softmax_csr<1><<<cdiv(Nn, 8), 256>>>(Nn);
        k_agg_csr<1, 512><<<Nn, 128>>>(h, b2, feat, Nn, 1);
    }

    // ---------------- Layer 3: 512 -> 121, 1 head, mean (=identity) ------
    {
        k_zero_dots<<<cdiv(Nn, 256), 256>>>(Nn);
        dim3 grid(cdiv(121, GBN), cdiv(Nn, GBM));
        k_gemm_tf32<<<grid, 256, GSMEM_BYTES>>>(feat, W3, h, Nn, 121, 512,
                                                a3s, a3d, 1, 121);
        k_softmax_csr<1><<<cdiv(Nn, 8), 256>>>(Nn);
        k_agg_csr_s<<<Nn, 128>>>(h, b3, out, Nn, 121);
    }
}